// round 6
// baseline (speedup 1.0000x reference)
#include <cuda_runtime.h>
#include <math.h>
#include <stdint.h>

// ---------------------------------------------------------------------------
// VQ-VAE forward, fp32 with packed f32x2 FFMA2 convolutions.
// Output layout (float32, 3145732 elems):
//   [0] e_and_q  [1..3145728] x_recon  [3145729] e_latent  [3145730] q_latent
//   [3145731] est_words
// ---------------------------------------------------------------------------

#define BATCH 64
#define VQ_K 512
#define VQ_D 64
#define OUT_RECON_OFF 1
#define OUT_RECON_N   (64*3*128*128)
#define OUT_ELQ  (OUT_RECON_OFF + OUT_RECON_N)
#define OUT_QLQ  (OUT_ELQ + 1)
#define OUT_EW   (OUT_QLQ + 1)

typedef unsigned long long ull;

// ---- packed f32x2 helpers --------------------------------------------------
__device__ __forceinline__ ull pk2(float lo, float hi) {
    ull r; asm("mov.b64 %0, {%1, %2};" : "=l"(r) : "f"(lo), "f"(hi)); return r;
}
__device__ __forceinline__ float2 unpk(ull v) {
    float2 r; asm("mov.b64 {%0, %1}, %2;" : "=f"(r.x), "=f"(r.y) : "l"(v)); return r;
}
__device__ __forceinline__ void fma2(ull& d, ull a, ull b) {
    asm("fma.rn.f32x2 %0, %1, %2, %0;" : "+l"(d) : "l"(a), "l"(b));
}

// ---------------- scratch buffers -------------------------------------------
__device__ float g_h1 [64*64*64*64];
__device__ float g_a  [64*128*32*32];
__device__ float g_b  [64*128*32*32];
__device__ float g_mid[64*64*32*32];
__device__ float g_ze [64*64*32*32];
__device__ float g_zq [64*64*32*32];
__device__ int   g_hist[VQ_K];
__device__ float g_mse[1];

__global__ void reset_k(int* hist, float* mse) {
    int t = threadIdx.x;
    if (t < VQ_K) hist[t] = 0;
    if (t == 0)   mse[0] = 0.f;
}

// ---------------------------------------------------------------------------
// 3x3 stride-1 pad-1 conv on 32x32 images, f32x2 packed, PRE-PACKED smem.
// grid(COUT/4, B), block 128. Thread tile 2oh x 4ow x 4oc; lanes = pw pairs.
//
// Shared input layout per ci (34 rows x 34 ull, row-major):
//   row r (= input row r-1, padded):
//     [0..16]  A-pairs: A[j] = (x[2j-1], x[2j])     smem cols (2j, 2j+1)
//     [18..33] M-pairs: M[j] = (x[2j],   x[2j+1])   smem cols (2j+1, 2j+2)
//   where x[] are input cols (pad = 0). Output pair (ow0+kw stencil):
//     kw=0 -> A[2t], A[2t+1]; kw=1 -> M[2t], M[2t+1]; kw=2 -> A[2t+1], A[2t+2]
// Chunks of 2 ci, double-buffered; one barrier per chunk.
// ---------------------------------------------------------------------------
template<int CIN, int COUT, bool PRE, bool POST, bool BIAS>
__global__ void __launch_bounds__(128, 4) conv3x3_k(
    const float* __restrict__ in, const float* __restrict__ w,
    const float* __restrict__ bias, float* __restrict__ out)
{
    const int n   = blockIdx.y;
    const int oc0 = blockIdx.x * 4;
    const int tid = threadIdx.x;
    const int oh0 = (tid >> 3) * 2;
    const int t   = tid & 7;

    __shared__ ull s_p [2][2][34 * 34];   // [buf][ci-in-chunk][r*34 + slot]
    __shared__ ull s_w2[2][2][4][10];     // [buf][ci-in-chunk][oc][tap] (padded)

    const float* inp   = in + (size_t)n * CIN * 1024;
    const float* wbase = w + (size_t)oc0 * CIN * 9;
    const int NC = CIN / 2;

    // ---- stage one channel plane into s_p[buf][j], pre-packed -------------
    auto stage_ci = [&](int buf, int j, int ci) {
        const float* ip = inp + (size_t)ci * 1024;
        ull* sp = s_p[buf][j];
        // A-pairs: 17 x 34
        for (int i = tid; i < 578; i += 128) {
            int r  = i / 17;
            int c2 = i - r * 17;
            int ih = r - 1;
            float lo = 0.f, hi = 0.f;
            if ((unsigned)ih < 32u) {
                int cl = 2 * c2 - 1;
                if ((unsigned)cl < 32u) lo = ip[ih * 32 + cl];
                if (2 * c2 < 32)        hi = ip[ih * 32 + 2 * c2];
            }
            if (PRE) { lo = fmaxf(lo, 0.f); hi = fmaxf(hi, 0.f); }
            sp[r * 34 + c2] = pk2(lo, hi);
        }
        // M-pairs: 16 x 34 (always col-in-bounds, aligned float2)
        for (int i = tid; i < 544; i += 128) {
            int r  = i >> 4;
            int c2 = i & 15;
            int ih = r - 1;
            float lo = 0.f, hi = 0.f;
            if ((unsigned)ih < 32u) {
                float2 v = *reinterpret_cast<const float2*>(ip + ih * 32 + 2 * c2);
                lo = v.x; hi = v.y;
            }
            if (PRE) { lo = fmaxf(lo, 0.f); hi = fmaxf(hi, 0.f); }
            sp[r * 34 + 18 + c2] = pk2(lo, hi);
        }
    };
    auto stage_w = [&](int buf, int ci0) {
        for (int i = tid; i < 72; i += 128) {
            int j  = i / 36;
            int r  = i - j * 36;
            int oc = r / 9, kk = r - oc * 9;
            float v = wbase[(size_t)oc * CIN * 9 + (ci0 + j) * 9 + kk];
            s_w2[buf][j][oc][kk] = pk2(v, v);
        }
    };

    stage_ci(0, 0, 0);
    stage_ci(0, 1, 1);
    stage_w(0, 0);
    __syncthreads();

    ull acc[4][2][2];
#pragma unroll
    for (int a = 0; a < 4; a++)
#pragma unroll
        for (int p = 0; p < 2; p++) { acc[a][p][0] = 0ULL; acc[a][p][1] = 0ULL; }

    for (int cc = 0; cc < NC; cc++) {
        const int buf = cc & 1;
        // prefetch next chunk
        if (cc + 1 < NC) {
            stage_ci(buf ^ 1, 0, (cc + 1) * 2);
            stage_ci(buf ^ 1, 1, (cc + 1) * 2 + 1);
            stage_w(buf ^ 1, (cc + 1) * 2);
        }

#pragma unroll
        for (int j = 0; j < 2; j++) {
            const ull* sp = s_p[buf][j];
            ull A[4][3], M[4][2];
#pragma unroll
            for (int r4 = 0; r4 < 4; r4++) {
                const ull* row = sp + (oh0 + r4) * 34;
                A[r4][0] = row[2 * t];
                A[r4][1] = row[2 * t + 1];
                A[r4][2] = row[2 * t + 2];
                M[r4][0] = row[18 + 2 * t];
                M[r4][1] = row[18 + 2 * t + 1];
            }
            const ull* wj = &s_w2[buf][j][0][0];
#pragma unroll
            for (int oc = 0; oc < 4; oc++)
#pragma unroll
                for (int kh = 0; kh < 3; kh++)
#pragma unroll
                    for (int kw = 0; kw < 3; kw++) {
                        ull w2 = wj[oc * 10 + kh * 3 + kw];
#pragma unroll
                        for (int ph = 0; ph < 2; ph++) {
                            int r = ph + kh;
                            ull p0 = (kw == 0) ? A[r][0] : ((kw == 1) ? M[r][0] : A[r][1]);
                            ull p1 = (kw == 0) ? A[r][1] : ((kw == 1) ? M[r][1] : A[r][2]);
                            fma2(acc[oc][ph][0], p0, w2);
                            fma2(acc[oc][ph][1], p1, w2);
                        }
                    }
        }
        __syncthreads();
    }

#pragma unroll
    for (int oc = 0; oc < 4; oc++) {
        float bv = BIAS ? bias[oc0 + oc] : 0.f;
        float* orow = out + ((size_t)(n * COUT + oc0 + oc)) * 1024 + oh0 * 32 + 4 * t;
#pragma unroll
        for (int ph = 0; ph < 2; ph++)
#pragma unroll
            for (int j2 = 0; j2 < 2; j2++) {
                float2 v = unpk(acc[oc][ph][j2]);
                v.x += bv; v.y += bv;
                if (POST) { v.x = fmaxf(v.x, 0.f); v.y = fmaxf(v.y, 0.f); }
                *reinterpret_cast<float2*>(orow + ph * 32 + 2 * j2) = v;
            }
    }
}

// ---------------------------------------------------------------------------
// 4x4 stride-2 pad-1 conv, f32x2 packed (lanes = oh pair).
// grid(COUT/4, (HOUT/32)^2, B), block 128. Dynamic smem:
//   [ull w2: CIN*4*16][float in: 2 x 66*66]
// ---------------------------------------------------------------------------
template<int CIN, int COUT, int HIN, int HOUT, bool POST>
__global__ void __launch_bounds__(128, 3) conv4x4s2_k(
    const float* __restrict__ in, const float* __restrict__ w,
    const float* __restrict__ bias, float* __restrict__ out)
{
    extern __shared__ char dsm[];
    ull*   s_w2  = (ull*)dsm;
    float* s_in0 = (float*)(dsm + (size_t)CIN * 4 * 16 * 8);
    float* s_in1 = s_in0 + 66 * 66;

    const int n   = blockIdx.z;
    const int oc0 = blockIdx.x * 4;
    const int TB  = HOUT / 32;
    const int r0  = (blockIdx.y / TB) * 32;
    const int c0  = (blockIdx.y % TB) * 32;
    const int tid = threadIdx.x;
    const int loh0 = (tid >> 3) * 2;
    const int low0 = (tid & 7) * 4;

    for (int i = tid; i < 4 * CIN * 16; i += 128) {
        int oc = i / (CIN * 16);
        int r  = i - oc * (CIN * 16);
        int ci = r / 16, kk = r - ci * 16;
        float v = w[(size_t)(oc0 + oc) * CIN * 16 + r];
        s_w2[(ci * 4 + oc) * 16 + kk] = pk2(v, v);
    }

    const int ihb = 2 * r0 - 1, iwb = 2 * c0 - 1;
    const float* inp = in + (size_t)n * CIN * HIN * HIN;

    for (int idx = tid; idx < 66 * 66; idx += 128) {
        int r = idx / 66, c = idx - r * 66;
        int ih = ihb + r, iw = iwb + c;
        float v = 0.f;
        if ((unsigned)ih < (unsigned)HIN && (unsigned)iw < (unsigned)HIN)
            v = inp[(size_t)ih * HIN + iw];
        s_in0[idx] = v;
    }
    __syncthreads();

    ull acc[4][4];
#pragma unroll
    for (int a = 0; a < 4; a++)
#pragma unroll
        for (int q = 0; q < 4; q++) acc[a][q] = 0ULL;

    for (int ci = 0; ci < CIN; ci++) {
        const float* cur = (ci & 1) ? s_in1 : s_in0;
        if (ci + 1 < CIN) {
            float* nb = ((ci + 1) & 1) ? s_in1 : s_in0;
            const float* inn = inp + (size_t)(ci + 1) * HIN * HIN;
            for (int idx = tid; idx < 66 * 66; idx += 128) {
                int r = idx / 66, c = idx - r * 66;
                int ih = ihb + r, iw = iwb + c;
                float v = 0.f;
                if ((unsigned)ih < (unsigned)HIN && (unsigned)iw < (unsigned)HIN)
                    v = inn[(size_t)ih * HIN + iw];
                nb[idx] = v;
            }
        }

        const int rowA0 = 2 * loh0;
        const int base  = 2 * low0;
        const ull* wci  = s_w2 + ci * 64;
#pragma unroll
        for (int kh = 0; kh < 4; kh++) {
            const float* pa = cur + (rowA0 + kh) * 66 + base;
            const float* pb = pa + 132;
            ull P[10];
#pragma unroll
            for (int c = 0; c < 10; c++) P[c] = pk2(pa[c], pb[c]);
#pragma unroll
            for (int oc = 0; oc < 4; oc++)
#pragma unroll
                for (int kw = 0; kw < 4; kw++) {
                    ull w2 = wci[oc * 16 + kh * 4 + kw];
#pragma unroll
                    for (int pw = 0; pw < 4; pw++)
                        fma2(acc[oc][pw], P[2 * pw + kw], w2);
                }
        }
        __syncthreads();
    }

#pragma unroll
    for (int oc = 0; oc < 4; oc++) {
        float bv = bias[oc0 + oc];
        float* obase = out + ((size_t)(n * COUT + oc0 + oc)) * HOUT * HOUT +
                       (size_t)(r0 + loh0) * HOUT + (c0 + low0);
#pragma unroll
        for (int pw = 0; pw < 4; pw++) {
            float2 v = unpk(acc[oc][pw]);
            v.x += bv; v.y += bv;
            if (POST) { v.x = fmaxf(v.x, 0.f); v.y = fmaxf(v.y, 0.f); }
            obase[pw]        = v.x;
            obase[HOUT + pw] = v.y;
        }
    }
}

// ---------------------------------------------------------------------------
// ConvTranspose2d k=4 s=2 p=1 (torch layout (CIN,COUT,4,4)), f32x2 packed.
// ---------------------------------------------------------------------------
template<int CIN, int COUT, int OCB, int HIN, int HOUT, bool PRE, bool POST>
__global__ void __launch_bounds__(128, 4) convT4x4s2_k(
    const float* __restrict__ in, const float* __restrict__ w,
    const float* __restrict__ bias, float* __restrict__ out)
{
    const int n   = blockIdx.z;
    const int oc0 = blockIdx.x * OCB;
    const int TB  = HOUT / 32;
    const int r0  = (blockIdx.y / TB) * 32;
    const int c0  = (blockIdx.y % TB) * 32;
    const int tid = threadIdx.x;
    const int loh0 = (tid >> 3) * 2;
    const int low0 = (tid & 7) * 4;

    __shared__ float s_in[2][18 * 18];
    __shared__ ull   s_w2[CIN * OCB * 8];

    for (int i = tid; i < CIN * OCB * 8; i += 128) {
        int per = OCB * 8;
        int ci = i / per;
        int r  = i - ci * per;
        int oc = r >> 3;
        int t  = r & 7;
        int kw = t >> 1, p = t & 1;
        const float* wb = w + ((size_t)ci * COUT + oc0 + oc) * 16;
        s_w2[i] = pk2(wb[(p * 2 + 1) * 4 + kw], wb[(p * 2) * 4 + kw]);
    }

    const int ihb = (r0 - 2) / 2;
    const int iwb = (c0 - 2) / 2;
    const float* inp = in + (size_t)n * CIN * HIN * HIN;

    int goff[3];
#pragma unroll
    for (int s = 0; s < 3; s++) {
        int idx = tid + s * 128;
        int r = idx / 18, c = idx - r * 18;
        int ih = ihb + r, iw = iwb + c;
        goff[s] = ((unsigned)ih < (unsigned)HIN && (unsigned)iw < (unsigned)HIN)
                      ? ih * HIN + iw : -1;
    }

    {
        float* b0 = s_in[0];
#pragma unroll
        for (int s = 0; s < 2; s++) {
            float v = (goff[s] >= 0) ? inp[goff[s]] : 0.f;
            if (PRE) v = fmaxf(v, 0.f);
            b0[tid + s * 128] = v;
        }
        if (tid < 68) {
            float v = (goff[2] >= 0) ? inp[goff[2]] : 0.f;
            if (PRE) v = fmaxf(v, 0.f);
            b0[tid + 256] = v;
        }
    }
    __syncthreads();

    ull acc[OCB][4];
#pragma unroll
    for (int a = 0; a < OCB; a++)
#pragma unroll
        for (int q = 0; q < 4; q++) acc[a][q] = 0ULL;

    const int rb = loh0 >> 1;
    const int cb = low0 >> 1;

    for (int ci = 0; ci < CIN; ci++) {
        const float* cur = s_in[ci & 1];
        if (ci + 1 < CIN) {
            const float* inn = inp + (size_t)(ci + 1) * HIN * HIN;
            float* nb = s_in[(ci + 1) & 1];
#pragma unroll
            for (int s = 0; s < 2; s++) {
                float v = (goff[s] >= 0) ? inn[goff[s]] : 0.f;
                if (PRE) v = fmaxf(v, 0.f);
                nb[tid + s * 128] = v;
            }
            if (tid < 68) {
                float v = (goff[2] >= 0) ? inn[goff[2]] : 0.f;
                if (PRE) v = fmaxf(v, 0.f);
                nb[tid + 256] = v;
            }
        }

        ull A[4], B[4];
#pragma unroll
        for (int c = 0; c < 4; c++) {
            float x0 = cur[rb * 18 + cb + c];
            float x1 = cur[(rb + 1) * 18 + cb + c];
            float x2 = cur[(rb + 2) * 18 + cb + c];
            A[c] = pk2(x1, x2);
            B[c] = pk2(x0, x1);
        }

        const ull* wci = s_w2 + ci * OCB * 8;
#pragma unroll
        for (int oc = 0; oc < OCB; oc++) {
            const ull* wp = wci + oc * 8;
#pragma unroll
            for (int pw = 0; pw < 4; pw++) {
                const int kwh = (pw & 1) ? 0 : 1;
                const int rh  = (pw >> 1) + 1 + (pw & 1);
                fma2(acc[oc][pw], A[rh],     wp[kwh * 2 + 0]);
                fma2(acc[oc][pw], B[rh],     wp[kwh * 2 + 1]);
                fma2(acc[oc][pw], A[rh - 1], wp[(kwh + 2) * 2 + 0]);
                fma2(acc[oc][pw], B[rh - 1], wp[(kwh + 2) * 2 + 1]);
            }
        }
        __syncthreads();
    }

#pragma unroll
    for (int oc = 0; oc < OCB; oc++) {
        float bv = bias[oc0 + oc];
        float* obase = out + ((size_t)(n * COUT + oc0 + oc)) * HOUT * HOUT +
                       (size_t)(r0 + loh0) * HOUT + (c0 + low0);
#pragma unroll
        for (int pw = 0; pw < 4; pw++) {
            float2 v = unpk(acc[oc][pw]);
            v.x += bv; v.y += bv;
            if (POST) { v.x = fmaxf(v.x, 0.f); v.y = fmaxf(v.y, 0.f); }
            obase[pw]        = v.x;
            obase[HOUT + pw] = v.y;
        }
    }
}

// ---------------------------------------------------------------------------
// 1x1 conv on 32x32 images.
// ---------------------------------------------------------------------------
template<int CIN, int COUT, bool PRE, bool BIAS, bool ADDRES>
__global__ void __launch_bounds__(256) conv1x1_k(
    const float* __restrict__ in, const float* __restrict__ w,
    const float* __restrict__ bias, float* __restrict__ out)
{
    const int n   = blockIdx.y;
    const int oc0 = blockIdx.x * 4;
    const int tid = threadIdx.x;
    const int hw0 = tid * 4;

    __shared__ float s_w[4 * CIN];
    for (int i = tid; i < 4 * CIN; i += 256)
        s_w[i] = w[(oc0 + i / CIN) * CIN + (i % CIN)];
    __syncthreads();

    float acc[4][4];
#pragma unroll
    for (int a = 0; a < 4; a++)
#pragma unroll
        for (int q = 0; q < 4; q++) acc[a][q] = 0.f;

    const float* inp = in + (size_t)n * CIN * 1024 + hw0;
    for (int ci = 0; ci < CIN; ci++) {
        float4 v = *reinterpret_cast<const float4*>(inp + (size_t)ci * 1024);
        if (PRE) {
            v.x = fmaxf(v.x, 0.f); v.y = fmaxf(v.y, 0.f);
            v.z = fmaxf(v.z, 0.f); v.w = fmaxf(v.w, 0.f);
        }
#pragma unroll
        for (int oc = 0; oc < 4; oc++) {
            float wv = s_w[oc * CIN + ci];
            acc[oc][0] = fmaf(v.x, wv, acc[oc][0]);
            acc[oc][1] = fmaf(v.y, wv, acc[oc][1]);
            acc[oc][2] = fmaf(v.z, wv, acc[oc][2]);
            acc[oc][3] = fmaf(v.w, wv, acc[oc][3]);
        }
    }

#pragma unroll
    for (int oc = 0; oc < 4; oc++) {
        float bv = BIAS ? bias[oc0 + oc] : 0.f;
        float* op = out + ((size_t)(n * COUT + oc0 + oc)) * 1024 + hw0;
        float4 o;
        o.x = acc[oc][0] + bv; o.y = acc[oc][1] + bv;
        o.z = acc[oc][2] + bv; o.w = acc[oc][3] + bv;
        if (ADDRES) {
            float4 r = *reinterpret_cast<const float4*>(op);
            o.x += r.x; o.y += r.y; o.z += r.z; o.w += r.w;
        }
        *reinterpret_cast<float4*>(op) = o;
    }
}

// ---------------------------------------------------------------------------
// Vector quantizer.
// ---------------------------------------------------------------------------
#define VQ_SMEM ((32768 + 512 + 512 + 256) * 4)

__global__ void __launch_bounds__(256) vq_k(
    const float* __restrict__ ze, const float* __restrict__ E,
    float* __restrict__ zq, int* __restrict__ hist, float* __restrict__ mse)
{
    extern __shared__ float sm[];
    float* sE   = sm;
    float* sEsq = sm + 32768;
    int*   sHist= (int*)(sm + 33280);
    float* sRed = sm + 33792;

    const int tid = threadIdx.x;
    for (int i = tid; i < VQ_K * VQ_D; i += 256) sE[i] = E[i];
    for (int i = tid; i < VQ_K; i += 256) sHist[i] = 0;
    __syncthreads();
    for (int i = tid; i < VQ_K; i += 256) {
        const float* e = &sE[i * VQ_D];
        float s = 0.f;
#pragma unroll 16
        for (int d = 0; d < VQ_D; d++) s = fmaf(e[d], e[d], s);
        sEsq[i] = s;
    }
    __syncthreads();

    const int p  = blockIdx.x * 256 + tid;
    const int n  = p >> 10;
    const int hw = p & 1023;
    const float* zp = ze + (size_t)n * VQ_D * 1024 + hw;

    float f[VQ_D];
#pragma unroll
    for (int d = 0; d < VQ_D; d++) f[d] = zp[(size_t)d * 1024];

    float best = 3.4e38f;
    int   bi   = 0;
    for (int k = 0; k < VQ_K; k++) {
        const float4* e4 = reinterpret_cast<const float4*>(&sE[k * VQ_D]);
        float s0 = 0.f, s1 = 0.f, s2 = 0.f, s3 = 0.f;
#pragma unroll
        for (int d = 0; d < VQ_D / 4; d++) {
            float4 e = e4[d];
            s0 = fmaf(e.x, f[4 * d + 0], s0);
            s1 = fmaf(e.y, f[4 * d + 1], s1);
            s2 = fmaf(e.z, f[4 * d + 2], s2);
            s3 = fmaf(e.w, f[4 * d + 3], s3);
        }
        float score = sEsq[k] - 2.f * ((s0 + s1) + (s2 + s3));
        if (score < best) { best = score; bi = k; }
    }

    const float* eb = &sE[bi * VQ_D];
    float* zqp = zq + (size_t)n * VQ_D * 1024 + hw;
    float md = 0.f;
#pragma unroll
    for (int d = 0; d < VQ_D; d++) {
        float ev = eb[d];
        float dd = f[d] - ev;
        md = fmaf(dd, dd, md);
        zqp[(size_t)d * 1024] = ev;
    }

    atomicAdd(&sHist[bi], 1);
    sRed[tid] = md;
    __syncthreads();
    for (int s = 128; s > 0; s >>= 1) {
        if (tid < s) sRed[tid] += sRed[tid + s];
        __syncthreads();
    }
    if (tid == 0) atomicAdd(mse, sRed[0]);
    for (int i = tid; i < VQ_K; i += 256) {
        int c = sHist[i];
        if (c) atomicAdd(&hist[i], c);
    }
}

__global__ void finalize_k(const int* __restrict__ hist,
                           const float* __restrict__ mse,
                           float* __restrict__ out)
{
    __shared__ float red[VQ_K];
    const int k = threadIdx.x;
    float pb = (float)hist[k] * (1.f / 65536.f);
    red[k] = pb * log2f(pb + 1e-10f);
    __syncthreads();
    for (int s = 256; s > 0; s >>= 1) {
        if (k < s) red[k] += red[k + s];
        __syncthreads();
    }
    if (k == 0) {
        float H = -red[0];
        float m = mse[0] * (1.f / (65536.f * 64.f));
        out[0]       = 1.25f * m;
        out[OUT_ELQ] = m;
        out[OUT_QLQ] = m;
        out[OUT_EW]  = exp2f(H);
    }
}

// ---------------------------------------------------------------------------
// Launch
// ---------------------------------------------------------------------------
extern "C" void kernel_launch(void* const* d_in, const int* in_sizes, int n_in,
                              void* d_out, int out_size)
{
    (void)in_sizes; (void)n_in; (void)out_size;
    const float* x          = (const float*)d_in[0];
    const float* enc_w1     = (const float*)d_in[1];
    const float* enc_b1     = (const float*)d_in[2];
    const float* enc_w2     = (const float*)d_in[3];
    const float* enc_b2     = (const float*)d_in[4];
    const float* enc_w3     = (const float*)d_in[5];
    const float* enc_b3     = (const float*)d_in[6];
    const float* enc_w4     = (const float*)d_in[7];
    const float* enc_b4     = (const float*)d_in[8];
    const float* enc_res_w1 = (const float*)d_in[9];
    const float* enc_res_w2 = (const float*)d_in[10];
    const float* enc_adj_w  = (const float*)d_in[11];
    const float* enc_adj_b  = (const float*)d_in[12];
    const float* E          = (const float*)d_in[13];
    const float* dec_adj_w  = (const float*)d_in[14];
    const float* dec_adj_b  = (const float*)d_in[15];
    const float* dec_res_w1 = (const float*)d_in[16];
    const float* dec_res_w2 = (const float*)d_in[17];
    const float* tc1_w      = (const float*)d_in[18];
    const float* tc1_b      = (const float*)d_in[19];
    const float* tc2_w      = (const float*)d_in[20];
    const float* tc2_b      = (const float*)d_in[21];
    float* out = (float*)d_out;

    float *h1, *a, *b, *mid, *ze, *zq, *mse; int* hist;
    cudaGetSymbolAddress((void**)&h1,  g_h1);
    cudaGetSymbolAddress((void**)&a,   g_a);
    cudaGetSymbolAddress((void**)&b,   g_b);
    cudaGetSymbolAddress((void**)&mid, g_mid);
    cudaGetSymbolAddress((void**)&ze,  g_ze);
    cudaGetSymbolAddress((void**)&zq,  g_zq);
    cudaGetSymbolAddress((void**)&mse, g_mse);
    cudaGetSymbolAddress((void**)&hist, g_hist);

    cudaFuncSetAttribute(vq_k, cudaFuncAttributeMaxDynamicSharedMemorySize, VQ_SMEM);

    const int SMEM_C1 = 3  * 4 * 16 * 8 + 2 * 66 * 66 * 4;   // 36384
    const int SMEM_C2 = 64 * 4 * 16 * 8 + 2 * 66 * 66 * 4;   // 67616
    cudaFuncSetAttribute(conv4x4s2_k<3, 64, 128, 64, true>,
                         cudaFuncAttributeMaxDynamicSharedMemorySize, SMEM_C1);
    cudaFuncSetAttribute(conv4x4s2_k<64, 128, 64, 32, true>,
                         cudaFuncAttributeMaxDynamicSharedMemorySize, SMEM_C2);

    reset_k<<<1, 512>>>(hist, mse);

    // ---- Encoder ----
    conv4x4s2_k<3, 64, 128, 64, true><<<dim3(16, 4, BATCH), 128, SMEM_C1>>>(x, enc_w1, enc_b1, h1);
    conv4x4s2_k<64, 128, 64, 32, true><<<dim3(32, 1, BATCH), 128, SMEM_C2>>>(h1, enc_w2, enc_b2, a);
    conv3x3_k<128, 128, false, true,  true><<<dim3(32, BATCH), 128>>>(a, enc_w3, enc_b3, b);
    conv3x3_k<128, 128, false, false, true><<<dim3(32, BATCH), 128>>>(b, enc_w4, enc_b4, a);
    conv3x3_k<128, 64, true, true, false><<<dim3(16, BATCH), 128>>>(a, enc_res_w1, nullptr, mid);
    conv1x1_k<64, 128, false, false, true><<<dim3(32, BATCH), 256>>>(mid, enc_res_w2, nullptr, a);
    conv3x3_k<128, 64, true, true, false><<<dim3(16, BATCH), 128>>>(a, enc_res_w1 + 64 * 128 * 9, nullptr, mid);
    conv1x1_k<64, 128, false, false, true><<<dim3(32, BATCH), 256>>>(mid, enc_res_w2 + 128 * 64, nullptr, a);
    conv1x1_k<128, 64, true, true, false><<<dim3(16, BATCH), 256>>>(a, enc_adj_w, enc_adj_b, ze);

    // ---- Vector quantizer ----
    vq_k<<<256, 256, VQ_SMEM>>>(ze, E, zq, hist, mse);
    finalize_k<<<1, 512>>>(hist, mse, out);

    // ---- Decoder ----
    conv3x3_k<64, 128, false, false, true><<<dim3(32, BATCH), 128>>>(zq, dec_adj_w, dec_adj_b, a);
    conv3x3_k<128, 64, true, true, false><<<dim3(16, BATCH), 128>>>(a, dec_res_w1, nullptr, mid);
    conv1x1_k<64, 128, false, false, true><<<dim3(32, BATCH), 256>>>(mid, dec_res_w2, nullptr, a);
    conv3x3_k<128, 64, true, true, false><<<dim3(16, BATCH), 128>>>(a, dec_res_w1 + 64 * 128 * 9, nullptr, mid);
    conv1x1_k<64, 128, false, false, true><<<dim3(32, BATCH), 256>>>(mid, dec_res_w2 + 128 * 64, nullptr, a);
    convT4x4s2_k<128, 64, 4, 32, 64, true, true><<<dim3(16, 4, BATCH), 128>>>(a, tc1_w, tc1_b, h1);
    convT4x4s2_k<64, 3, 3, 64, 128, false, false><<<dim3(1, 16, BATCH), 128>>>(h1, tc2_w, tc2_b, out + OUT_RECON_OFF);
}

// round 7
// speedup vs baseline: 1.4563x; 1.4563x over previous
#include <cuda_runtime.h>
#include <math.h>
#include <stdint.h>

// ---------------------------------------------------------------------------
// VQ-VAE forward, fp32 with packed f32x2 FFMA2 convolutions.
// Output layout (float32, 3145732 elems):
//   [0] e_and_q  [1..3145728] x_recon  [3145729] e_latent  [3145730] q_latent
//   [3145731] est_words
// ---------------------------------------------------------------------------

#define BATCH 64
#define VQ_K 512
#define VQ_D 64
#define OUT_RECON_OFF 1
#define OUT_RECON_N   (64*3*128*128)
#define OUT_ELQ  (OUT_RECON_OFF + OUT_RECON_N)
#define OUT_QLQ  (OUT_ELQ + 1)
#define OUT_EW   (OUT_QLQ + 1)

typedef unsigned long long ull;

// ---- packed f32x2 helpers --------------------------------------------------
__device__ __forceinline__ ull pk2(float lo, float hi) {
    ull r; asm("mov.b64 %0, {%1, %2};" : "=l"(r) : "f"(lo), "f"(hi)); return r;
}
__device__ __forceinline__ float2 unpk(ull v) {
    float2 r; asm("mov.b64 {%0, %1}, %2;" : "=f"(r.x), "=f"(r.y) : "l"(v)); return r;
}
__device__ __forceinline__ void fma2(ull& d, ull a, ull b) {
    asm("fma.rn.f32x2 %0, %1, %2, %0;" : "+l"(d) : "l"(a), "l"(b));
}

// ---------------- scratch buffers -------------------------------------------
__device__ float g_h1 [64*64*64*64];
__device__ float g_a  [64*128*32*32];
__device__ float g_b  [64*128*32*32];
__device__ float g_mid[64*64*32*32];
__device__ float g_ze [64*64*32*32];
__device__ float g_zq [64*64*32*32];
__device__ int   g_hist[VQ_K];
__device__ float g_mse[1];

__global__ void reset_k(int* hist, float* mse) {
    int t = threadIdx.x;
    if (t < VQ_K) hist[t] = 0;
    if (t == 0)   mse[0] = 0.f;
}

// ---------------------------------------------------------------------------
// 3x3 stride-1 pad-1 conv on 32x32 images, f32x2 packed, 4 oc per block.
// grid(COUT/4, B), block 128. Thread tile 2oh x 4ow x 4oc; lanes = pw pairs.
// Input + weights double-buffered in chunks of 2 ci; one barrier per chunk.
// smem ~20KB -> occupancy register-limited; cap at 5 CTAs (102 regs).
// ---------------------------------------------------------------------------
template<int CIN, int COUT, bool PRE, bool POST, bool BIAS>
__global__ void __launch_bounds__(128, 5) conv3x3_k(
    const float* __restrict__ in, const float* __restrict__ w,
    const float* __restrict__ bias, float* __restrict__ out)
{
    const int n   = blockIdx.y;
    const int oc0 = blockIdx.x * 4;
    const int tid = threadIdx.x;
    const int oh0 = (tid >> 3) * 2;
    const int ow0 = (tid & 7) * 4;

    __shared__ float s_in[2][2 * 1156];   // [buf][ci-in-chunk * 34*34]
    __shared__ ull   s_w2[2][72];         // [buf][ci2*36 + oc*9 + kk]

    // staging gmem offsets within one channel plane, -1 = pad
    int goff[10];
#pragma unroll
    for (int s = 0; s < 10; s++) {
        int idx = tid + s * 128;
        int r = idx / 34, c = idx - r * 34;
        int ih = r - 1, iw = c - 1;
        goff[s] = ((unsigned)ih < 32u && (unsigned)iw < 32u) ? ih * 32 + iw : -1;
    }
    const float* inp   = in + (size_t)n * CIN * 1024;
    const float* wbase = w + (size_t)oc0 * CIN * 9;

    const int NC = CIN / 2;

    // ---- stage one 2-ci chunk (input planes + weights) ---------------------
    auto stage_chunk = [&](int buf, int ci0) {
#pragma unroll
        for (int j = 0; j < 2; j++) {
            const float* ip = inp + (size_t)(ci0 + j) * 1024;
            float* dst = s_in[buf] + j * 1156;
#pragma unroll
            for (int s = 0; s < 9; s++) {
                float v = (goff[s] >= 0) ? ip[goff[s]] : 0.f;
                if (PRE) v = fmaxf(v, 0.f);
                dst[tid + s * 128] = v;
            }
            if (tid < 4) {
                float v = (goff[9] >= 0) ? ip[goff[9]] : 0.f;
                if (PRE) v = fmaxf(v, 0.f);
                dst[tid + 1152] = v;
            }
        }
        if (tid < 72) {
            int j  = tid / 36;
            int r  = tid - j * 36;
            int oc = r / 9, kk = r - oc * 9;
            float v = wbase[(size_t)oc * CIN * 9 + (ci0 + j) * 9 + kk];
            s_w2[buf][tid] = pk2(v, v);
        }
    };

    stage_chunk(0, 0);
    __syncthreads();

    ull acc[4][2][2];
#pragma unroll
    for (int a = 0; a < 4; a++)
#pragma unroll
        for (int p = 0; p < 2; p++) { acc[a][p][0] = 0ULL; acc[a][p][1] = 0ULL; }

    for (int cc = 0; cc < NC; cc++) {
        const int buf = cc & 1;
        if (cc + 1 < NC) stage_chunk(buf ^ 1, (cc + 1) * 2);

#pragma unroll
        for (int j = 0; j < 2; j++) {
            const float* cur = s_in[buf] + j * 1156;
            ull Ar[4][3], Mr[4][2];
#pragma unroll
            for (int r = 0; r < 4; r++) {
                const float* p = cur + (oh0 + r) * 34 + ow0;
                float2 q0 = *reinterpret_cast<const float2*>(p);
                float2 q1 = *reinterpret_cast<const float2*>(p + 2);
                float2 q2 = *reinterpret_cast<const float2*>(p + 4);
                Ar[r][0] = pk2(q0.x, q0.y);
                Ar[r][1] = pk2(q1.x, q1.y);
                Ar[r][2] = pk2(q2.x, q2.y);
                Mr[r][0] = pk2(q0.y, q1.x);
                Mr[r][1] = pk2(q1.y, q2.x);
            }
            const ull* wj = s_w2[buf] + j * 36;
#pragma unroll
            for (int oc = 0; oc < 4; oc++)
#pragma unroll
                for (int kh = 0; kh < 3; kh++)
#pragma unroll
                    for (int kw = 0; kw < 3; kw++) {
                        ull w2 = wj[oc * 9 + kh * 3 + kw];
#pragma unroll
                        for (int ph = 0; ph < 2; ph++) {
                            int r = ph + kh;
                            ull p0 = (kw == 0) ? Ar[r][0] : ((kw == 1) ? Mr[r][0] : Ar[r][1]);
                            ull p1 = (kw == 0) ? Ar[r][1] : ((kw == 1) ? Mr[r][1] : Ar[r][2]);
                            fma2(acc[oc][ph][0], p0, w2);
                            fma2(acc[oc][ph][1], p1, w2);
                        }
                    }
        }
        __syncthreads();
    }

#pragma unroll
    for (int oc = 0; oc < 4; oc++) {
        float bv = BIAS ? bias[oc0 + oc] : 0.f;
        float* orow = out + ((size_t)(n * COUT + oc0 + oc)) * 1024 + oh0 * 32 + ow0;
#pragma unroll
        for (int ph = 0; ph < 2; ph++)
#pragma unroll
            for (int j2 = 0; j2 < 2; j2++) {
                float2 v = unpk(acc[oc][ph][j2]);
                v.x += bv; v.y += bv;
                if (POST) { v.x = fmaxf(v.x, 0.f); v.y = fmaxf(v.y, 0.f); }
                *reinterpret_cast<float2*>(orow + ph * 32 + 2 * j2) = v;
            }
    }
}

// ---------------------------------------------------------------------------
// 4x4 stride-2 pad-1 conv, f32x2 packed (lanes = oh pair).
// grid(COUT/4, (HOUT/32)^2, B), block 128. Dynamic smem:
//   [ull w2: CIN*4*16][float in: 2 x 66*66]
// ---------------------------------------------------------------------------
template<int CIN, int COUT, int HIN, int HOUT, bool POST>
__global__ void __launch_bounds__(128, 3) conv4x4s2_k(
    const float* __restrict__ in, const float* __restrict__ w,
    const float* __restrict__ bias, float* __restrict__ out)
{
    extern __shared__ char dsm[];
    ull*   s_w2  = (ull*)dsm;
    float* s_in0 = (float*)(dsm + (size_t)CIN * 4 * 16 * 8);
    float* s_in1 = s_in0 + 66 * 66;

    const int n   = blockIdx.z;
    const int oc0 = blockIdx.x * 4;
    const int TB  = HOUT / 32;
    const int r0  = (blockIdx.y / TB) * 32;
    const int c0  = (blockIdx.y % TB) * 32;
    const int tid = threadIdx.x;
    const int loh0 = (tid >> 3) * 2;
    const int low0 = (tid & 7) * 4;

    for (int i = tid; i < 4 * CIN * 16; i += 128) {
        int oc = i / (CIN * 16);
        int r  = i - oc * (CIN * 16);
        int ci = r / 16, kk = r - ci * 16;
        float v = w[(size_t)(oc0 + oc) * CIN * 16 + r];
        s_w2[(ci * 4 + oc) * 16 + kk] = pk2(v, v);
    }

    const int ihb = 2 * r0 - 1, iwb = 2 * c0 - 1;
    const float* inp = in + (size_t)n * CIN * HIN * HIN;

    for (int idx = tid; idx < 66 * 66; idx += 128) {
        int r = idx / 66, c = idx - r * 66;
        int ih = ihb + r, iw = iwb + c;
        float v = 0.f;
        if ((unsigned)ih < (unsigned)HIN && (unsigned)iw < (unsigned)HIN)
            v = inp[(size_t)ih * HIN + iw];
        s_in0[idx] = v;
    }
    __syncthreads();

    ull acc[4][4];
#pragma unroll
    for (int a = 0; a < 4; a++)
#pragma unroll
        for (int q = 0; q < 4; q++) acc[a][q] = 0ULL;

    for (int ci = 0; ci < CIN; ci++) {
        const float* cur = (ci & 1) ? s_in1 : s_in0;
        if (ci + 1 < CIN) {
            float* nb = ((ci + 1) & 1) ? s_in1 : s_in0;
            const float* inn = inp + (size_t)(ci + 1) * HIN * HIN;
            for (int idx = tid; idx < 66 * 66; idx += 128) {
                int r = idx / 66, c = idx - r * 66;
                int ih = ihb + r, iw = iwb + c;
                float v = 0.f;
                if ((unsigned)ih < (unsigned)HIN && (unsigned)iw < (unsigned)HIN)
                    v = inn[(size_t)ih * HIN + iw];
                nb[idx] = v;
            }
        }

        const int rowA0 = 2 * loh0;
        const int base  = 2 * low0;
        const ull* wci  = s_w2 + ci * 64;
#pragma unroll
        for (int kh = 0; kh < 4; kh++) {
            const float* pa = cur + (rowA0 + kh) * 66 + base;
            const float* pb = pa + 132;
            ull P[10];
#pragma unroll
            for (int c = 0; c < 10; c++) P[c] = pk2(pa[c], pb[c]);
#pragma unroll
            for (int oc = 0; oc < 4; oc++)
#pragma unroll
                for (int kw = 0; kw < 4; kw++) {
                    ull w2 = wci[oc * 16 + kh * 4 + kw];
#pragma unroll
                    for (int pw = 0; pw < 4; pw++)
                        fma2(acc[oc][pw], P[2 * pw + kw], w2);
                }
        }
        __syncthreads();
    }

#pragma unroll
    for (int oc = 0; oc < 4; oc++) {
        float bv = bias[oc0 + oc];
        float* obase = out + ((size_t)(n * COUT + oc0 + oc)) * HOUT * HOUT +
                       (size_t)(r0 + loh0) * HOUT + (c0 + low0);
#pragma unroll
        for (int pw = 0; pw < 4; pw++) {
            float2 v = unpk(acc[oc][pw]);
            v.x += bv; v.y += bv;
            if (POST) { v.x = fmaxf(v.x, 0.f); v.y = fmaxf(v.y, 0.f); }
            obase[pw]        = v.x;
            obase[HOUT + pw] = v.y;
        }
    }
}

// ---------------------------------------------------------------------------
// ConvTranspose2d k=4 s=2 p=1 (torch layout (CIN,COUT,4,4)), f32x2 packed.
// ---------------------------------------------------------------------------
template<int CIN, int COUT, int OCB, int HIN, int HOUT, bool PRE, bool POST>
__global__ void __launch_bounds__(128, 4) convT4x4s2_k(
    const float* __restrict__ in, const float* __restrict__ w,
    const float* __restrict__ bias, float* __restrict__ out)
{
    const int n   = blockIdx.z;
    const int oc0 = blockIdx.x * OCB;
    const int TB  = HOUT / 32;
    const int r0  = (blockIdx.y / TB) * 32;
    const int c0  = (blockIdx.y % TB) * 32;
    const int tid = threadIdx.x;
    const int loh0 = (tid >> 3) * 2;
    const int low0 = (tid & 7) * 4;

    __shared__ float s_in[2][18 * 18];
    __shared__ ull   s_w2[CIN * OCB * 8];

    for (int i = tid; i < CIN * OCB * 8; i += 128) {
        int per = OCB * 8;
        int ci = i / per;
        int r  = i - ci * per;
        int oc = r >> 3;
        int t  = r & 7;
        int kw = t >> 1, p = t & 1;
        const float* wb = w + ((size_t)ci * COUT + oc0 + oc) * 16;
        s_w2[i] = pk2(wb[(p * 2 + 1) * 4 + kw], wb[(p * 2) * 4 + kw]);
    }

    const int ihb = (r0 - 2) / 2;
    const int iwb = (c0 - 2) / 2;
    const float* inp = in + (size_t)n * CIN * HIN * HIN;

    int goff[3];
#pragma unroll
    for (int s = 0; s < 3; s++) {
        int idx = tid + s * 128;
        int r = idx / 18, c = idx - r * 18;
        int ih = ihb + r, iw = iwb + c;
        goff[s] = ((unsigned)ih < (unsigned)HIN && (unsigned)iw < (unsigned)HIN)
                      ? ih * HIN + iw : -1;
    }

    {
        float* b0 = s_in[0];
#pragma unroll
        for (int s = 0; s < 2; s++) {
            float v = (goff[s] >= 0) ? inp[goff[s]] : 0.f;
            if (PRE) v = fmaxf(v, 0.f);
            b0[tid + s * 128] = v;
        }
        if (tid < 68) {
            float v = (goff[2] >= 0) ? inp[goff[2]] : 0.f;
            if (PRE) v = fmaxf(v, 0.f);
            b0[tid + 256] = v;
        }
    }
    __syncthreads();

    ull acc[OCB][4];
#pragma unroll
    for (int a = 0; a < OCB; a++)
#pragma unroll
        for (int q = 0; q < 4; q++) acc[a][q] = 0ULL;

    const int rb = loh0 >> 1;
    const int cb = low0 >> 1;

    for (int ci = 0; ci < CIN; ci++) {
        const float* cur = s_in[ci & 1];
        if (ci + 1 < CIN) {
            const float* inn = inp + (size_t)(ci + 1) * HIN * HIN;
            float* nb = s_in[(ci + 1) & 1];
#pragma unroll
            for (int s = 0; s < 2; s++) {
                float v = (goff[s] >= 0) ? inn[goff[s]] : 0.f;
                if (PRE) v = fmaxf(v, 0.f);
                nb[tid + s * 128] = v;
            }
            if (tid < 68) {
                float v = (goff[2] >= 0) ? inn[goff[2]] : 0.f;
                if (PRE) v = fmaxf(v, 0.f);
                nb[tid + 256] = v;
            }
        }

        ull A[4], B[4];
#pragma unroll
        for (int c = 0; c < 4; c++) {
            float x0 = cur[rb * 18 + cb + c];
            float x1 = cur[(rb + 1) * 18 + cb + c];
            float x2 = cur[(rb + 2) * 18 + cb + c];
            A[c] = pk2(x1, x2);
            B[c] = pk2(x0, x1);
        }

        const ull* wci = s_w2 + ci * OCB * 8;
#pragma unroll
        for (int oc = 0; oc < OCB; oc++) {
            const ull* wp = wci + oc * 8;
#pragma unroll
            for (int pw = 0; pw < 4; pw++) {
                const int kwh = (pw & 1) ? 0 : 1;
                const int rh  = (pw >> 1) + 1 + (pw & 1);
                fma2(acc[oc][pw], A[rh],     wp[kwh * 2 + 0]);
                fma2(acc[oc][pw], B[rh],     wp[kwh * 2 + 1]);
                fma2(acc[oc][pw], A[rh - 1], wp[(kwh + 2) * 2 + 0]);
                fma2(acc[oc][pw], B[rh - 1], wp[(kwh + 2) * 2 + 1]);
            }
        }
        __syncthreads();
    }

#pragma unroll
    for (int oc = 0; oc < OCB; oc++) {
        float bv = bias[oc0 + oc];
        float* obase = out + ((size_t)(n * COUT + oc0 + oc)) * HOUT * HOUT +
                       (size_t)(r0 + loh0) * HOUT + (c0 + low0);
#pragma unroll
        for (int pw = 0; pw < 4; pw++) {
            float2 v = unpk(acc[oc][pw]);
            v.x += bv; v.y += bv;
            if (POST) { v.x = fmaxf(v.x, 0.f); v.y = fmaxf(v.y, 0.f); }
            obase[pw]        = v.x;
            obase[HOUT + pw] = v.y;
        }
    }
}

// ---------------------------------------------------------------------------
// 1x1 conv on 32x32 images.
// ---------------------------------------------------------------------------
template<int CIN, int COUT, bool PRE, bool BIAS, bool ADDRES>
__global__ void __launch_bounds__(256) conv1x1_k(
    const float* __restrict__ in, const float* __restrict__ w,
    const float* __restrict__ bias, float* __restrict__ out)
{
    const int n   = blockIdx.y;
    const int oc0 = blockIdx.x * 4;
    const int tid = threadIdx.x;
    const int hw0 = tid * 4;

    __shared__ float s_w[4 * CIN];
    for (int i = tid; i < 4 * CIN; i += 256)
        s_w[i] = w[(oc0 + i / CIN) * CIN + (i % CIN)];
    __syncthreads();

    float acc[4][4];
#pragma unroll
    for (int a = 0; a < 4; a++)
#pragma unroll
        for (int q = 0; q < 4; q++) acc[a][q] = 0.f;

    const float* inp = in + (size_t)n * CIN * 1024 + hw0;
    for (int ci = 0; ci < CIN; ci++) {
        float4 v = *reinterpret_cast<const float4*>(inp + (size_t)ci * 1024);
        if (PRE) {
            v.x = fmaxf(v.x, 0.f); v.y = fmaxf(v.y, 0.f);
            v.z = fmaxf(v.z, 0.f); v.w = fmaxf(v.w, 0.f);
        }
#pragma unroll
        for (int oc = 0; oc < 4; oc++) {
            float wv = s_w[oc * CIN + ci];
            acc[oc][0] = fmaf(v.x, wv, acc[oc][0]);
            acc[oc][1] = fmaf(v.y, wv, acc[oc][1]);
            acc[oc][2] = fmaf(v.z, wv, acc[oc][2]);
            acc[oc][3] = fmaf(v.w, wv, acc[oc][3]);
        }
    }

#pragma unroll
    for (int oc = 0; oc < 4; oc++) {
        float bv = BIAS ? bias[oc0 + oc] : 0.f;
        float* op = out + ((size_t)(n * COUT + oc0 + oc)) * 1024 + hw0;
        float4 o;
        o.x = acc[oc][0] + bv; o.y = acc[oc][1] + bv;
        o.z = acc[oc][2] + bv; o.w = acc[oc][3] + bv;
        if (ADDRES) {
            float4 r = *reinterpret_cast<const float4*>(op);
            o.x += r.x; o.y += r.y; o.z += r.z; o.w += r.w;
        }
        *reinterpret_cast<float4*>(op) = o;
    }
}

// ---------------------------------------------------------------------------
// Vector quantizer.
// ---------------------------------------------------------------------------
#define VQ_SMEM ((32768 + 512 + 512 + 256) * 4)

__global__ void __launch_bounds__(256) vq_k(
    const float* __restrict__ ze, const float* __restrict__ E,
    float* __restrict__ zq, int* __restrict__ hist, float* __restrict__ mse)
{
    extern __shared__ float sm[];
    float* sE   = sm;
    float* sEsq = sm + 32768;
    int*   sHist= (int*)(sm + 33280);
    float* sRed = sm + 33792;

    const int tid = threadIdx.x;
    for (int i = tid; i < VQ_K * VQ_D; i += 256) sE[i] = E[i];
    for (int i = tid; i < VQ_K; i += 256) sHist[i] = 0;
    __syncthreads();
    for (int i = tid; i < VQ_K; i += 256) {
        const float* e = &sE[i * VQ_D];
        float s = 0.f;
#pragma unroll 16
        for (int d = 0; d < VQ_D; d++) s = fmaf(e[d], e[d], s);
        sEsq[i] = s;
    }
    __syncthreads();

    const int p  = blockIdx.x * 256 + tid;
    const int n  = p >> 10;
    const int hw = p & 1023;
    const float* zp = ze + (size_t)n * VQ_D * 1024 + hw;

    float f[VQ_D];
#pragma unroll
    for (int d = 0; d < VQ_D; d++) f[d] = zp[(size_t)d * 1024];

    float best = 3.4e38f;
    int   bi   = 0;
    for (int k = 0; k < VQ_K; k++) {
        const float4* e4 = reinterpret_cast<const float4*>(&sE[k * VQ_D]);
        float s0 = 0.f, s1 = 0.f, s2 = 0.f, s3 = 0.f;
#pragma unroll
        for (int d = 0; d < VQ_D / 4; d++) {
            float4 e = e4[d];
            s0 = fmaf(e.x, f[4 * d + 0], s0);
            s1 = fmaf(e.y, f[4 * d + 1], s1);
            s2 = fmaf(e.z, f[4 * d + 2], s2);
            s3 = fmaf(e.w, f[4 * d + 3], s3);
        }
        float score = sEsq[k] - 2.f * ((s0 + s1) + (s2 + s3));
        if (score < best) { best = score; bi = k; }
    }

    const float* eb = &sE[bi * VQ_D];
    float* zqp = zq + (size_t)n * VQ_D * 1024 + hw;
    float md = 0.f;
#pragma unroll
    for (int d = 0; d < VQ_D; d++) {
        float ev = eb[d];
        float dd = f[d] - ev;
        md = fmaf(dd, dd, md);
        zqp[(size_t)d * 1024] = ev;
    }

    atomicAdd(&sHist[bi], 1);
    sRed[tid] = md;
    __syncthreads();
    for (int s = 128; s > 0; s >>= 1) {
        if (tid < s) sRed[tid] += sRed[tid + s];
        __syncthreads();
    }
    if (tid == 0) atomicAdd(mse, sRed[0]);
    for (int i = tid; i < VQ_K; i += 256) {
        int c = sHist[i];
        if (c) atomicAdd(&hist[i], c);
    }
}

__global__ void finalize_k(const int* __restrict__ hist,
                           const float* __restrict__ mse,
                           float* __restrict__ out)
{
    __shared__ float red[VQ_K];
    const int k = threadIdx.x;
    float pb = (float)hist[k] * (1.f / 65536.f);
    red[k] = pb * log2f(pb + 1e-10f);
    __syncthreads();
    for (int s = 256; s > 0; s >>= 1) {
        if (k < s) red[k] += red[k + s];
        __syncthreads();
    }
    if (k == 0) {
        float H = -red[0];
        float m = mse[0] * (1.f / (65536.f * 64.f));
        out[0]       = 1.25f * m;
        out[OUT_ELQ] = m;
        out[OUT_QLQ] = m;
        out[OUT_EW]  = exp2f(H);
    }
}

// ---------------------------------------------------------------------------
// Launch
// ---------------------------------------------------------------------------
extern "C" void kernel_launch(void* const* d_in, const int* in_sizes, int n_in,
                              void* d_out, int out_size)
{
    (void)in_sizes; (void)n_in; (void)out_size;
    const float* x          = (const float*)d_in[0];
    const float* enc_w1     = (const float*)d_in[1];
    const float* enc_b1     = (const float*)d_in[2];
    const float* enc_w2     = (const float*)d_in[3];
    const float* enc_b2     = (const float*)d_in[4];
    const float* enc_w3     = (const float*)d_in[5];
    const float* enc_b3     = (const float*)d_in[6];
    const float* enc_w4     = (const float*)d_in[7];
    const float* enc_b4     = (const float*)d_in[8];
    const float* enc_res_w1 = (const float*)d_in[9];
    const float* enc_res_w2 = (const float*)d_in[10];
    const float* enc_adj_w  = (const float*)d_in[11];
    const float* enc_adj_b  = (const float*)d_in[12];
    const float* E          = (const float*)d_in[13];
    const float* dec_adj_w  = (const float*)d_in[14];
    const float* dec_adj_b  = (const float*)d_in[15];
    const float* dec_res_w1 = (const float*)d_in[16];
    const float* dec_res_w2 = (const float*)d_in[17];
    const float* tc1_w      = (const float*)d_in[18];
    const float* tc1_b      = (const float*)d_in[19];
    const float* tc2_w      = (const float*)d_in[20];
    const float* tc2_b      = (const float*)d_in[21];
    float* out = (float*)d_out;

    float *h1, *a, *b, *mid, *ze, *zq, *mse; int* hist;
    cudaGetSymbolAddress((void**)&h1,  g_h1);
    cudaGetSymbolAddress((void**)&a,   g_a);
    cudaGetSymbolAddress((void**)&b,   g_b);
    cudaGetSymbolAddress((void**)&mid, g_mid);
    cudaGetSymbolAddress((void**)&ze,  g_ze);
    cudaGetSymbolAddress((void**)&zq,  g_zq);
    cudaGetSymbolAddress((void**)&mse, g_mse);
    cudaGetSymbolAddress((void**)&hist, g_hist);

    cudaFuncSetAttribute(vq_k, cudaFuncAttributeMaxDynamicSharedMemorySize, VQ_SMEM);

    const int SMEM_C1 = 3  * 4 * 16 * 8 + 2 * 66 * 66 * 4;   // 36384
    const int SMEM_C2 = 64 * 4 * 16 * 8 + 2 * 66 * 66 * 4;   // 67616
    cudaFuncSetAttribute(conv4x4s2_k<3, 64, 128, 64, true>,
                         cudaFuncAttributeMaxDynamicSharedMemorySize, SMEM_C1);
    cudaFuncSetAttribute(conv4x4s2_k<64, 128, 64, 32, true>,
                         cudaFuncAttributeMaxDynamicSharedMemorySize, SMEM_C2);

    reset_k<<<1, 512>>>(hist, mse);

    // ---- Encoder ----
    conv4x4s2_k<3, 64, 128, 64, true><<<dim3(16, 4, BATCH), 128, SMEM_C1>>>(x, enc_w1, enc_b1, h1);
    conv4x4s2_k<64, 128, 64, 32, true><<<dim3(32, 1, BATCH), 128, SMEM_C2>>>(h1, enc_w2, enc_b2, a);
    conv3x3_k<128, 128, false, true,  true><<<dim3(32, BATCH), 128>>>(a, enc_w3, enc_b3, b);
    conv3x3_k<128, 128, false, false, true><<<dim3(32, BATCH), 128>>>(b, enc_w4, enc_b4, a);
    conv3x3_k<128, 64, true, true, false><<<dim3(16, BATCH), 128>>>(a, enc_res_w1, nullptr, mid);
    conv1x1_k<64, 128, false, false, true><<<dim3(32, BATCH), 256>>>(mid, enc_res_w2, nullptr, a);
    conv3x3_k<128, 64, true, true, false><<<dim3(16, BATCH), 128>>>(a, enc_res_w1 + 64 * 128 * 9, nullptr, mid);
    conv1x1_k<64, 128, false, false, true><<<dim3(32, BATCH), 256>>>(mid, enc_res_w2 + 128 * 64, nullptr, a);
    conv1x1_k<128, 64, true, true, false><<<dim3(16, BATCH), 256>>>(a, enc_adj_w, enc_adj_b, ze);

    // ---- Vector quantizer ----
    vq_k<<<256, 256, VQ_SMEM>>>(ze, E, zq, hist, mse);
    finalize_k<<<1, 512>>>(hist, mse, out);

    // ---- Decoder ----
    conv3x3_k<64, 128, false, false, true><<<dim3(32, BATCH), 128>>>(zq, dec_adj_w, dec_adj_b, a);
    conv3x3_k<128, 64, true, true, false><<<dim3(16, BATCH), 128>>>(a, dec_res_w1, nullptr, mid);
    conv1x1_k<64, 128, false, false, true><<<dim3(32, BATCH), 256>>>(mid, dec_res_w2, nullptr, a);
    conv3x3_k<128, 64, true, true, false><<<dim3(16, BATCH), 128>>>(a, dec_res_w1 + 64 * 128 * 9, nullptr, mid);
    conv1x1_k<64, 128, false, false, true><<<dim3(32, BATCH), 256>>>(mid, dec_res_w2 + 128 * 64, nullptr, a);
    convT4x4s2_k<128, 64, 4, 32, 64, true, true><<<dim3(16, 4, BATCH), 128>>>(a, tc1_w, tc1_b, h1);
    convT4x4s2_k<64, 3, 3, 64, 128, false, false><<<dim3(1, 16, BATCH), 128>>>(h1, tc2_w, tc2_b, out + OUT_RECON_OFF);
}